// round 5
// baseline (speedup 1.0000x reference)
#include <cuda_runtime.h>
#include <cstdint>
#include <cstddef>

#define NN 30000
#define EE 480000
#define CC 32
#define NTT 15
#define EPSF 1e-8f

// ---------------- scratch (static device globals; no allocation) ----------------
__device__ float g_geoP[(size_t)EE * 12];       // CSR-ordered: r, Y1[3], Y2[5], pad[3]
__device__ float g_blk[(size_t)EE * 160];       // CSR-ordered: m0, a1=w3*f0s, w4, a2=w5*f0s, w6
__device__ float g_logits[EE * 4];              // CSR-ordered
__device__ float g_v[(size_t)NN * 128];         // permuted per-node attention vectors
__device__ float g_M[2][32 * 128];              // fused Wq@Wk^T per head, permuted
__device__ float g_f0[2][NN * CC];
__device__ float g_f1[2][NN * CC * 3];
__device__ float g_f2[2][NN * CC * 5];
__device__ int   g_cnt[NN];
__device__ int   g_rowptr[NN + 1];
__device__ int   g_cursor[NN];
__device__ int   g_eid[EE];                     // p -> e (for edge_feat gather)
__device__ int   g_srcp[EE];                    // p -> src node
__device__ int   g_dstp[EE];                    // p -> dst node

#define FULL 0xffffffffu

// ---------------- f32x2 packed helpers ----------------
__device__ __forceinline__ unsigned long long pk2(float lo, float hi) {
    unsigned long long r;
    asm("mov.b64 %0, {%1, %2};" : "=l"(r) : "f"(lo), "f"(hi));
    return r;
}
__device__ __forceinline__ void unpk(unsigned long long v, float& lo, float& hi) {
    asm("mov.b64 {%0, %1}, %2;" : "=f"(lo), "=f"(hi) : "l"(v));
}
__device__ __forceinline__ unsigned long long dup2(float v) {
    unsigned long long r;
    asm("mov.b64 %0, {%1, %1};" : "=l"(r) : "f"(v));
    return r;
}
__device__ __forceinline__ unsigned long long fma2(unsigned long long a, unsigned long long b,
                                                   unsigned long long c) {
    unsigned long long d;
    asm("fma.rn.f32x2 %0, %1, %2, %3;" : "=l"(d) : "l"(a), "l"(b), "l"(c));
    return d;
}

// ---------------- fused attention matrices: M[l][h] = (Wq_h * 1/sqrt8) @ Wk_h^T ----------------
// layout baked for edge kernel: g_M[l][c*128 + j], j = k*32+lane encodes (h=lane>>3, c'=(lane&7)+8k)
__global__ void __launch_bounds__(256) mprep_kernel(const float* __restrict__ Wq,
                                                    const float* __restrict__ Wk) {
    int t = threadIdx.x;
    int l = t >> 7, j = t & 127;
    int lane = j & 31, k = j >> 5;
    int h = lane >> 3, cp = (lane & 7) + 8 * k;
    const float* wq = Wq + l * 1024;
    const float* wk = Wk + l * 1024;
#pragma unroll 4
    for (int c = 0; c < 32; c++) {
        float acc = 0.0f;
#pragma unroll
        for (int dh = 0; dh < 8; dh++)
            acc = fmaf(wq[c * 32 + h * 8 + dh], wk[cp * 32 + h * 8 + dh], acc);
        g_M[l][c * 128 + j] = acc * 0.35355339059327373f;
    }
}

// ---------------- degree histogram ----------------
__global__ void __launch_bounds__(256) hist_kernel(const int* __restrict__ dst) {
    int e = blockIdx.x * 256 + threadIdx.x;
    if (e >= EE) return;
    atomicAdd(&g_cnt[dst[e]], 1);
}

// ---------------- single-block exclusive scan (also re-zeroes counts for replay) ----------------
__global__ void __launch_bounds__(1024) scan_kernel() {
    __shared__ int ssum[1024];
    const int CH = 30;
    int t = threadIdx.x;
    int start = t * CH;
    int s = 0;
    for (int i = 0; i < CH; i++) {
        int idx = start + i;
        if (idx < NN) s += g_cnt[idx];
    }
    ssum[t] = s;
    __syncthreads();
    for (int off = 1; off < 1024; off <<= 1) {
        int v = (t >= off) ? ssum[t - off] : 0;
        __syncthreads();
        ssum[t] += v;
        __syncthreads();
    }
    int run = (t == 0) ? 0 : ssum[t - 1];
    for (int i = 0; i < CH; i++) {
        int idx = start + i;
        if (idx < NN) {
            g_rowptr[idx] = run;
            g_cursor[idx] = run;
            run += g_cnt[idx];
            g_cnt[idx] = 0;       // restore invariant for next graph replay
        }
    }
    if (t == 0) g_rowptr[NN] = EE;
}

// ---------------- scatter + geometry into CSR order ----------------
__global__ void __launch_bounds__(256) scatter_geo_kernel(const float* __restrict__ pos,
                                                          const int* __restrict__ src,
                                                          const int* __restrict__ dst) {
    int e = blockIdx.x * 256 + threadIdx.x;
    if (e >= EE) return;
    int s = src[e], d = dst[e];
    int p = atomicAdd(&g_cursor[d], 1);
    g_eid[p] = e;
    g_srcp[p] = s;
    g_dstp[p] = d;
    float rx = pos[d * 3 + 0] - pos[s * 3 + 0];
    float ry = pos[d * 3 + 1] - pos[s * 3 + 1];
    float rz = pos[d * 3 + 2] - pos[s * 3 + 2];
    float r = sqrtf(rx * rx + ry * ry + rz * rz + EPSF);
    float inv = 1.0f / r;
    float x = rx * inv, y = ry * inv, z = rz * inv;
    float4* gp = (float4*)&g_geoP[(size_t)p * 12];
    gp[0] = make_float4(r, x, y, z);
    gp[1] = make_float4(x * y, y * z, 3.0f * z * z - 1.0f, x * z);
    gp[2] = make_float4(x * x - y * y, 0.0f, 0.0f, 0.0f);
}

// ---------------- per-node attention vectors: v = f0 @ M (pre-permuted) ----------------
__global__ void __launch_bounds__(256) vn_kernel(const float* __restrict__ Ml,
                                                 const float* __restrict__ f0src) {
    __shared__ float sM[32 * 128];
    int tid = threadIdx.x;
    for (int i = tid; i < 32 * 128; i += 256) sM[i] = Ml[i];
    __syncthreads();
    int lane = tid & 31;
    int n = blockIdx.x * 8 + (tid >> 5);
    float f = f0src[n * CC + lane];
    float o0 = 0, o1 = 0, o2 = 0, o3 = 0;
#pragma unroll
    for (int c = 0; c < 32; c++) {
        float fc = __shfl_sync(FULL, f, c);
        const float* m = &sM[c * 128 + lane];
        o0 = fmaf(fc, m[0], o0);
        o1 = fmaf(fc, m[32], o1);
        o2 = fmaf(fc, m[64], o2);
        o3 = fmaf(fc, m[96], o3);
    }
    float* vp = &g_v[(size_t)n * 128 + lane];
    vp[0] = o0; vp[32] = o1; vp[64] = o2; vp[96] = o3;
}

// ---------------- edge kernel: 8 edges per warp, CSR order, f32x2 radial MLP ----------------
template <bool FIRST>
__global__ void __launch_bounds__(256) edge_kernel(const float* __restrict__ edge_feat,
                                                   const float* __restrict__ Wr1,
                                                   const float* __restrict__ br1,
                                                   const float* __restrict__ Wr2,
                                                   const float* __restrict__ f0src,
                                                   const float* __restrict__ f1src,
                                                   const float* __restrict__ f2src) {
    __shared__ float sWr1[33 * 32];
    __shared__ float sbr1[32];
    __shared__ float sWr2[32 * 224];
    int tid = threadIdx.x;
    for (int i = tid; i < 33 * 32; i += 256) sWr1[i] = Wr1[i];
    if (tid < 32) sbr1[tid] = br1[tid];
    for (int i = tid; i < 32 * 224; i += 256) sWr2[i] = Wr2[i];
    __syncthreads();

    int wid = tid >> 5, lane = tid & 31;
    int wstride = gridDim.x * 8;
    const int NGROUP = EE / 8;

    for (int g = blockIdx.x * 8 + wid; g < NGROUP; g += wstride) {
        int p8 = g * 8;

        // gather feats (random 128B lines via eid) and r (sequential)
        unsigned long long fp[4];
        float rr[8];
#pragma unroll
        for (int j = 0; j < 4; j++) {
            int ea = g_eid[p8 + 2 * j];
            int eb = g_eid[p8 + 2 * j + 1];
            fp[j] = pk2(edge_feat[(size_t)ea * CC + lane], edge_feat[(size_t)eb * CC + lane]);
        }
#pragma unroll
        for (int pe = 0; pe < 8; pe++) rr[pe] = g_geoP[(size_t)(p8 + pe) * 12];

        // hidden = relu([r,feat] @ Wr1 + b)
        float hb = sbr1[lane];
        float w0l = sWr1[lane];
        unsigned long long h[4];
#pragma unroll
        for (int j = 0; j < 4; j++)
            h[j] = pk2(fmaf(rr[2 * j], w0l, hb), fmaf(rr[2 * j + 1], w0l, hb));
#pragma unroll
        for (int i = 0; i < 32; i++) {
            unsigned long long wd = dup2(sWr1[(i + 1) * 32 + lane]);
#pragma unroll
            for (int j = 0; j < 4; j++)
                h[j] = fma2(__shfl_sync(FULL, fp[j], i), wd, h[j]);
        }
#pragma unroll
        for (int j = 0; j < 4; j++) {
            float a, b;
            unpk(h[j], a, b);
            h[j] = pk2(fmaxf(a, 0.f), fmaxf(b, 0.f));
        }

        // w = hidden @ Wr2 : 7 outputs/lane x 8 edges
        unsigned long long W[4][7];
#pragma unroll
        for (int j = 0; j < 4; j++)
#pragma unroll
            for (int p = 0; p < 7; p++) W[j][p] = 0ull;
#pragma unroll
        for (int i = 0; i < 32; i++) {
            unsigned long long hs0 = __shfl_sync(FULL, h[0], i);
            unsigned long long hs1 = __shfl_sync(FULL, h[1], i);
            unsigned long long hs2 = __shfl_sync(FULL, h[2], i);
            unsigned long long hs3 = __shfl_sync(FULL, h[3], i);
            const float* wr = &sWr2[i * 224 + lane];
#pragma unroll
            for (int p = 0; p < 7; p++) {
                unsigned long long wd = dup2(wr[p * 32]);
                W[0][p] = fma2(hs0, wd, W[0][p]);
                W[1][p] = fma2(hs1, wd, W[1][p]);
                W[2][p] = fma2(hs2, wd, W[2][p]);
                W[3][p] = fma2(hs3, wd, W[3][p]);
            }
        }

        // per-edge message + logits
#pragma unroll
        for (int pe = 0; pe < 8; pe++) {
            float wv[7];
#pragma unroll
            for (int p = 0; p < 7; p++) {
                float lo, hi;
                unpk(W[pe >> 1][p], lo, hi);
                wv[p] = (pe & 1) ? hi : lo;
            }
            int p = p8 + pe;
            int s = g_srcp[p];
            int d = g_dstp[p];
            float f0s = f0src[(size_t)s * CC + lane];
            float m0;
            if (FIRST) {
                m0 = wv[0] * f0s;
            } else {
                const float4 ga = *(const float4*)&g_geoP[(size_t)p * 12];
                const float4 gb = *(const float4*)&g_geoP[(size_t)p * 12 + 4];
                float Y24 = g_geoP[(size_t)p * 12 + 8];
                const float* p1 = &f1src[(size_t)s * 96 + lane];
                float f1a = p1[0], f1b = p1[32], f1c = p1[64];
                const float* p2 = &f2src[(size_t)s * 160 + lane];
                float f2a = p2[0], f2b = p2[32], f2c = p2[64], f2d = p2[96], f2e = p2[128];
                float dot1 = f1a * ga.y + f1b * ga.z + f1c * ga.w;
                float dot2 = f2a * gb.x + f2b * gb.y + f2c * gb.z + f2d * gb.w + f2e * Y24;
                m0 = wv[0] * f0s + wv[1] * dot1 + wv[2] * dot2;
            }
            float* blk = &g_blk[(size_t)p * 160];
            blk[lane]      = m0;
            blk[32 + lane] = wv[3] * f0s;
            blk[96 + lane] = wv[5] * f0s;
            if (!FIRST) {
                blk[64 + lane]  = wv[4];
                blk[128 + lane] = wv[6];
            }
            // logits: 8-lane group per head
            float acc = 0.0f;
#pragma unroll
            for (int k = 0; k < 4; k++) {
                float mv = __shfl_sync(FULL, m0, (lane & 7) + 8 * k);
                acc = fmaf(mv, __ldg(&g_v[(size_t)d * 128 + k * 32 + lane]), acc);
            }
            acc += __shfl_xor_sync(FULL, acc, 4);
            acc += __shfl_xor_sync(FULL, acc, 2);
            acc += __shfl_xor_sync(FULL, acc, 1);
            if ((lane & 7) == 0) g_logits[p * 4 + (lane >> 3)] = acc;
        }
    }
}

// ---------------- warp-per-node: streaming softmax + aggregate + self-mix ----------------
template <bool FIRST>
__global__ void __launch_bounds__(256) agg_kernel(const float* __restrict__ Ws0,
                                                  const float* __restrict__ Ws1,
                                                  const float* __restrict__ Ws2,
                                                  const float* __restrict__ Wsk,
                                                  const float* __restrict__ f1src,
                                                  const float* __restrict__ f2src,
                                                  const float* __restrict__ f0old,
                                                  float* __restrict__ f0out,
                                                  float* __restrict__ f1out,
                                                  float* __restrict__ f2out) {
    __shared__ float sW0[1024], sW1[1024], sW2[1024], sWkm[1024];
    __shared__ float sAcc[8][320];
    int tid = threadIdx.x;
    for (int i = tid; i < 1024; i += 256) {
        sW0[i] = Ws0[i]; sW1[i] = Ws1[i]; sW2[i] = Ws2[i]; sWkm[i] = Wsk[i];
    }
    __syncthreads();

    int wid = tid >> 5, lane = tid & 31;
    int n = blockIdx.x * 8 + wid;
    int beg = g_rowptr[n], end = g_rowptr[n + 1];
    int deg = end - beg;

    float mx0 = -1e30f, mx1 = -1e30f, mx2 = -1e30f, mx3 = -1e30f;
    for (int j = lane; j < deg; j += 32) {
        float4 lg = *(const float4*)&g_logits[(beg + j) * 4];
        mx0 = fmaxf(mx0, lg.x); mx1 = fmaxf(mx1, lg.y);
        mx2 = fmaxf(mx2, lg.z); mx3 = fmaxf(mx3, lg.w);
    }
#pragma unroll
    for (int o = 16; o > 0; o >>= 1) {
        mx0 = fmaxf(mx0, __shfl_xor_sync(FULL, mx0, o));
        mx1 = fmaxf(mx1, __shfl_xor_sync(FULL, mx1, o));
        mx2 = fmaxf(mx2, __shfl_xor_sync(FULL, mx2, o));
        mx3 = fmaxf(mx3, __shfl_xor_sync(FULL, mx3, o));
    }
    float d0 = 0, d1 = 0, d2 = 0, d3 = 0;
    for (int j = lane; j < deg; j += 32) {
        float4 lg = *(const float4*)&g_logits[(beg + j) * 4];
        d0 += expf(lg.x - mx0); d1 += expf(lg.y - mx1);
        d2 += expf(lg.z - mx2); d3 += expf(lg.w - mx3);
    }
#pragma unroll
    for (int o = 16; o > 0; o >>= 1) {
        d0 += __shfl_xor_sync(FULL, d0, o);
        d1 += __shfl_xor_sync(FULL, d1, o);
        d2 += __shfl_xor_sync(FULL, d2, o);
        d3 += __shfl_xor_sync(FULL, d3, o);
    }
    int h = lane >> 3;
    float mxh  = (h == 0) ? mx0 : (h == 1) ? mx1 : (h == 2) ? mx2 : mx3;
    float invh = 1.0f / (((h == 0) ? d0 : (h == 1) ? d1 : (h == 2) ? d2 : d3) + EPSF);

    float A0 = 0, A10 = 0, A11 = 0, A12 = 0;
    float A20 = 0, A21 = 0, A22 = 0, A23 = 0, A24 = 0;
#pragma unroll 2
    for (int j = 0; j < deg; j++) {
        int p = beg + j;
        float al = expf(g_logits[p * 4 + h] - mxh) * invh;
        const float* blk = &g_blk[(size_t)p * 160];
        float m0 = blk[lane];
        float a1 = blk[32 + lane];
        float a2 = blk[96 + lane];
        const float4 ga = __ldg((const float4*)&g_geoP[(size_t)p * 12]);
        const float4 gb = __ldg((const float4*)&g_geoP[(size_t)p * 12 + 4]);
        float Y24 = __ldg(&g_geoP[(size_t)p * 12 + 8]);
        A0 = fmaf(al, m0, A0);
        float t1 = al * a1, t2 = al * a2;
        A10 = fmaf(t1, ga.y, A10); A11 = fmaf(t1, ga.z, A11); A12 = fmaf(t1, ga.w, A12);
        A20 = fmaf(t2, gb.x, A20); A21 = fmaf(t2, gb.y, A21);
        A22 = fmaf(t2, gb.z, A22); A23 = fmaf(t2, gb.w, A23); A24 = fmaf(t2, Y24, A24);
        if (!FIRST) {
            float t4 = al * blk[64 + lane];
            float t6 = al * blk[128 + lane];
            int s = __ldg(&g_srcp[p]);
            const float* p1 = &f1src[(size_t)s * 96 + lane];
            A10 = fmaf(t4, p1[0], A10); A11 = fmaf(t4, p1[32], A11); A12 = fmaf(t4, p1[64], A12);
            const float* p2 = &f2src[(size_t)s * 160 + lane];
            A20 = fmaf(t6, p2[0], A20);  A21 = fmaf(t6, p2[32], A21);
            A22 = fmaf(t6, p2[64], A22); A23 = fmaf(t6, p2[96], A23); A24 = fmaf(t6, p2[128], A24);
        }
    }

    float* sa = sAcc[wid];
    sa[lane]        = A0;
    sa[32 + lane]   = A10;
    sa[64 + lane]   = A11;
    sa[96 + lane]   = A12;
    sa[128 + lane]  = A20;
    sa[160 + lane]  = A21;
    sa[192 + lane]  = A22;
    sa[224 + lane]  = A23;
    sa[256 + lane]  = A24;
    sa[288 + lane]  = f0old[n * CC + lane];
    __syncwarp();

    float o0 = 0, o10 = 0, o11 = 0, o12 = 0;
    float o20 = 0, o21 = 0, o22 = 0, o23 = 0, o24 = 0;
#pragma unroll
    for (int c = 0; c < 32; c++) {
        float w0v = sW0[c * 32 + lane], wkv = sWkm[c * 32 + lane];
        float w1v = sW1[c * 32 + lane], w2v = sW2[c * 32 + lane];
        o0  = fmaf(sa[c], w0v, fmaf(sa[288 + c], wkv, o0));
        o10 = fmaf(sa[32 + c],  w1v, o10);
        o11 = fmaf(sa[64 + c],  w1v, o11);
        o12 = fmaf(sa[96 + c],  w1v, o12);
        o20 = fmaf(sa[128 + c], w2v, o20);
        o21 = fmaf(sa[160 + c], w2v, o21);
        o22 = fmaf(sa[192 + c], w2v, o22);
        o23 = fmaf(sa[224 + c], w2v, o23);
        o24 = fmaf(sa[256 + c], w2v, o24);
    }
    f0out[n * CC + lane] = o0;
    f1out[n * 96 + lane]       = o10;
    f1out[n * 96 + 32 + lane]  = o11;
    f1out[n * 96 + 64 + lane]  = o12;
    f2out[n * 160 + lane]        = o20;
    f2out[n * 160 + 32 + lane]   = o21;
    f2out[n * 160 + 64 + lane]   = o22;
    f2out[n * 160 + 96 + lane]   = o23;
    f2out[n * 160 + 128 + lane]  = o24;
}

// ---------------- final projection ----------------
__global__ void __launch_bounds__(256) out_kernel(const float* __restrict__ Wout,
                                                  const float* __restrict__ Wc,
                                                  const float* __restrict__ f0,
                                                  float* __restrict__ out) {
    __shared__ float sWo[1024];
    __shared__ float sWc[32 * NTT];
    int tid = threadIdx.x;
    for (int i = tid; i < 1024; i += 256) sWo[i] = Wout[i];
    for (int i = tid; i < 32 * NTT; i += 256) sWc[i] = Wc[i];
    __syncthreads();
    int lane = tid & 31;
    int n = blockIdx.x * 8 + (tid >> 5);
    float f = f0[n * CC + lane];
    float hs = 0.0f;
#pragma unroll
    for (int c = 0; c < 32; c++)
        hs = fmaf(__shfl_sync(FULL, f, c), sWo[c * 32 + lane], hs);
    out[n * CC + lane] = hs;
    float cs = 0.0f;
#pragma unroll
    for (int c = 0; c < 32; c++) {
        float hv = __shfl_sync(FULL, hs, c);
        float wc = (lane < NTT) ? sWc[c * NTT + lane] : 0.0f;
        cs = fmaf(hv, wc, cs);
    }
    if (lane < NTT) out[NN * CC + n * NTT + lane] = cs;
}

// ---------------- host ----------------
extern "C" void kernel_launch(void* const* d_in, const int* in_sizes, int n_in,
                              void* d_out, int out_size) {
    const float* pos       = (const float*)d_in[0];
    const float* node_l0   = (const float*)d_in[1];
    const float* edge_feat = (const float*)d_in[2];
    const int*   edge_src  = (const int*)d_in[3];
    const int*   edge_dst  = (const int*)d_in[4];
    const float* Wr1       = (const float*)d_in[5];
    const float* br1       = (const float*)d_in[6];
    const float* Wr2       = (const float*)d_in[7];
    const float* Wq        = (const float*)d_in[8];
    const float* Wk        = (const float*)d_in[9];
    const float* Ws0       = (const float*)d_in[10];
    const float* Ws1       = (const float*)d_in[11];
    const float* Ws2       = (const float*)d_in[12];
    const float* Wsk       = (const float*)d_in[13];
    const float* Wout      = (const float*)d_in[14];
    const float* Wc        = (const float*)d_in[15];
    float* out = (float*)d_out;

    void *pf0, *pf1, *pf2, *pM;
    cudaGetSymbolAddress(&pf0, g_f0);
    cudaGetSymbolAddress(&pf1, g_f1);
    cudaGetSymbolAddress(&pf2, g_f2);
    cudaGetSymbolAddress(&pM, g_M);
    float* f0a = (float*)pf0;
    float* f0b = f0a + (size_t)NN * CC;
    float* f1a = (float*)pf1;
    float* f1b = f1a + (size_t)NN * CC * 3;
    float* f2a = (float*)pf2;
    float* f2b = f2a + (size_t)NN * CC * 5;
    float* M0 = (float*)pM;
    float* M1 = M0 + 32 * 128;

    // launch order chosen so ncu (-s 5 -c 1) captures the first edge_kernel
    mprep_kernel<<<1, 256>>>(Wq, Wk);                               // 0
    hist_kernel<<<EE / 256, 256>>>(edge_dst);                      // 1
    scan_kernel<<<1, 1024>>>();                                    // 2
    scatter_geo_kernel<<<EE / 256, 256>>>(pos, edge_src, edge_dst);// 3

    // ---- layer 0 (f1 = f2 = 0) ----
    vn_kernel<<<NN / 8, 256>>>(M0, node_l0);                       // 4
    edge_kernel<true><<<296, 256>>>(edge_feat, Wr1, br1, Wr2,      // 5  <- ncu capture
                                    node_l0, nullptr, nullptr);
    agg_kernel<true><<<NN / 8, 256>>>(Ws0, Ws1, Ws2, Wsk,
                                      nullptr, nullptr, node_l0, f0a, f1a, f2a);

    // ---- layer 1 ----
    vn_kernel<<<NN / 8, 256>>>(M1, f0a);
    edge_kernel<false><<<296, 256>>>(edge_feat, Wr1 + 33 * 32, br1 + 32, Wr2 + 32 * 224,
                                     f0a, f1a, f2a);
    agg_kernel<false><<<NN / 8, 256>>>(Ws0 + 1024, Ws1 + 1024, Ws2 + 1024, Wsk + 1024,
                                       f1a, f2a, f0a, f0b, f1b, f2b);

    out_kernel<<<NN / 8, 256>>>(Wout, Wc, f0b, out);
}

// round 7
// speedup vs baseline: 1.0722x; 1.0722x over previous
#include <cuda_runtime.h>
#include <cstdint>
#include <cstddef>

#define NN 30000
#define EE 480000
#define CC 32
#define NTT 15
#define EPSF 1e-8f

// ---------------- scratch (static device globals; no allocation) ----------------
__device__ float g_geoE[(size_t)EE * 12];       // by original edge e: r, Y1[3], Y2[5], pad
__device__ float g_geoP[(size_t)EE * 12];       // CSR-ordered copy for agg
__device__ float g_blk[(size_t)EE * 160];       // CSR-ordered: m0, w3*f0s, w4, w5*f0s, w6
__device__ float g_logits[EE * 4];              // CSR-ordered
__device__ float g_v[(size_t)NN * 128];         // permuted per-node attention vectors
__device__ float g_M[2][32 * 128];              // fused Wq@Wk^T per head, permuted
__device__ float g_f0[2][NN * CC];
__device__ float g_f1[2][NN * CC * 3];
__device__ float g_f2[2][NN * CC * 5];
__device__ int   g_cnt[NN];
__device__ int   g_rowptr[NN + 1];
__device__ int   g_cursor[NN];
__device__ int   g_pose[EE];                    // e -> CSR position p
__device__ int   g_srcp[EE];                    // p -> src node (for agg layer-1 gathers)

#define FULL 0xffffffffu

// ---------------- f32x2 packed helpers ----------------
__device__ __forceinline__ unsigned long long pk2(float lo, float hi) {
    unsigned long long r;
    asm("mov.b64 %0, {%1, %2};" : "=l"(r) : "f"(lo), "f"(hi));
    return r;
}
__device__ __forceinline__ void unpk(unsigned long long v, float& lo, float& hi) {
    asm("mov.b64 {%0, %1}, %2;" : "=f"(lo), "=f"(hi) : "l"(v));
}
__device__ __forceinline__ unsigned long long dup2(float v) {
    unsigned long long r;
    asm("mov.b64 %0, {%1, %1};" : "=l"(r) : "f"(v));
    return r;
}
__device__ __forceinline__ unsigned long long fma2(unsigned long long a, unsigned long long b,
                                                   unsigned long long c) {
    unsigned long long d;
    asm("fma.rn.f32x2 %0, %1, %2, %3;" : "=l"(d) : "l"(a), "l"(b), "l"(c));
    return d;
}

// ---------------- fused attention matrices ----------------
__global__ void __launch_bounds__(256) mprep_kernel(const float* __restrict__ Wq,
                                                    const float* __restrict__ Wk) {
    int t = threadIdx.x;
    int l = t >> 7, j = t & 127;
    int lane = j & 31, k = j >> 5;
    int h = lane >> 3, cp = (lane & 7) + 8 * k;
    const float* wq = Wq + l * 1024;
    const float* wk = Wk + l * 1024;
#pragma unroll 4
    for (int c = 0; c < 32; c++) {
        float acc = 0.0f;
#pragma unroll
        for (int dh = 0; dh < 8; dh++)
            acc = fmaf(wq[c * 32 + h * 8 + dh], wk[cp * 32 + h * 8 + dh], acc);
        g_M[l][c * 128 + j] = acc * 0.35355339059327373f;
    }
}

// ---------------- degree histogram ----------------
__global__ void __launch_bounds__(256) hist_kernel(const int* __restrict__ dst) {
    int e = blockIdx.x * 256 + threadIdx.x;
    if (e >= EE) return;
    atomicAdd(&g_cnt[dst[e]], 1);
}

// ---------------- single-block scan (re-zeroes counts for graph replay) ----------------
__global__ void __launch_bounds__(1024) scan_kernel() {
    __shared__ int ssum[1024];
    const int CH = 30;
    int t = threadIdx.x;
    int start = t * CH;
    int s = 0;
    for (int i = 0; i < CH; i++) {
        int idx = start + i;
        if (idx < NN) s += g_cnt[idx];
    }
    ssum[t] = s;
    __syncthreads();
    for (int off = 1; off < 1024; off <<= 1) {
        int v = (t >= off) ? ssum[t - off] : 0;
        __syncthreads();
        ssum[t] += v;
        __syncthreads();
    }
    int run = (t == 0) ? 0 : ssum[t - 1];
    for (int i = 0; i < CH; i++) {
        int idx = start + i;
        if (idx < NN) {
            g_rowptr[idx] = run;
            g_cursor[idx] = run;
            run += g_cnt[idx];
            g_cnt[idx] = 0;
        }
    }
    if (t == 0) g_rowptr[NN] = EE;
}

// ---------------- scatter + geometry (writes geo by-e sequential AND by-p) ----------------
__global__ void __launch_bounds__(256) scatter_geo_kernel(const float* __restrict__ pos,
                                                          const int* __restrict__ src,
                                                          const int* __restrict__ dst) {
    int e = blockIdx.x * 256 + threadIdx.x;
    if (e >= EE) return;
    int s = src[e], d = dst[e];
    int p = atomicAdd(&g_cursor[d], 1);
    g_pose[e] = p;
    g_srcp[p] = s;
    float rx = pos[d * 3 + 0] - pos[s * 3 + 0];
    float ry = pos[d * 3 + 1] - pos[s * 3 + 1];
    float rz = pos[d * 3 + 2] - pos[s * 3 + 2];
    float r = sqrtf(rx * rx + ry * ry + rz * rz + EPSF);
    float inv = 1.0f / r;
    float x = rx * inv, y = ry * inv, z = rz * inv;
    float4 a = make_float4(r, x, y, z);
    float4 b = make_float4(x * y, y * z, 3.0f * z * z - 1.0f, x * z);
    float4 c = make_float4(x * x - y * y, 0.0f, 0.0f, 0.0f);
    float4* ge = (float4*)&g_geoE[(size_t)e * 12];
    ge[0] = a; ge[1] = b; ge[2] = c;
    float4* gp = (float4*)&g_geoP[(size_t)p * 12];
    gp[0] = a; gp[1] = b; gp[2] = c;
}

// ---------------- per-node attention vectors: v = f0 @ M ----------------
__global__ void __launch_bounds__(256) vn_kernel(const float* __restrict__ Ml,
                                                 const float* __restrict__ f0src) {
    __shared__ float sM[32 * 128];
    int tid = threadIdx.x;
    for (int i = tid; i < 32 * 128; i += 256) sM[i] = Ml[i];
    __syncthreads();
    int lane = tid & 31;
    int n = blockIdx.x * 8 + (tid >> 5);
    float f = f0src[n * CC + lane];
    float o0 = 0, o1 = 0, o2 = 0, o3 = 0;
#pragma unroll
    for (int c = 0; c < 32; c++) {
        float fc = __shfl_sync(FULL, f, c);
        const float* m = &sM[c * 128 + lane];
        o0 = fmaf(fc, m[0], o0);
        o1 = fmaf(fc, m[32], o1);
        o2 = fmaf(fc, m[64], o2);
        o3 = fmaf(fc, m[96], o3);
    }
    float* vp = &g_v[(size_t)n * 128 + lane];
    vp[0] = o0; vp[32] = o1; vp[64] = o2; vp[96] = o3;
}

// ---------------- edge kernel: 4 edges/warp, sequential reads, CSR scatter writes ----------------
template <bool FIRST>
__global__ void __launch_bounds__(256) edge_kernel(const float* __restrict__ edge_feat,
                                                   const int* __restrict__ src,
                                                   const int* __restrict__ dst,
                                                   const float* __restrict__ Wr1,
                                                   const float* __restrict__ br1,
                                                   const float* __restrict__ Wr2,
                                                   const float* __restrict__ f0src,
                                                   const float* __restrict__ f1src,
                                                   const float* __restrict__ f2src) {
    __shared__ float sWr1[33 * 32];
    __shared__ float sbr1[32];
    __shared__ float sWr2[32 * 224];
    int tid = threadIdx.x;
    for (int i = tid; i < 33 * 32; i += 256) sWr1[i] = Wr1[i];
    if (tid < 32) sbr1[tid] = br1[tid];
    for (int i = tid; i < 32 * 224; i += 256) sWr2[i] = Wr2[i];
    __syncthreads();

    int wid = tid >> 5, lane = tid & 31;
    int wstride = gridDim.x * 8;

    for (int g = blockIdx.x * 8 + wid; g < EE / 4; g += wstride) {
        int e4 = g * 4;

        float feat0 = edge_feat[(size_t)(e4 + 0) * CC + lane];
        float feat1 = edge_feat[(size_t)(e4 + 1) * CC + lane];
        float feat2 = edge_feat[(size_t)(e4 + 2) * CC + lane];
        float feat3 = edge_feat[(size_t)(e4 + 3) * CC + lane];
        unsigned long long fp01 = pk2(feat0, feat1);
        unsigned long long fp23 = pk2(feat2, feat3);
        float r0 = g_geoE[(size_t)(e4 + 0) * 12];
        float r1 = g_geoE[(size_t)(e4 + 1) * 12];
        float r2 = g_geoE[(size_t)(e4 + 2) * 12];
        float r3 = g_geoE[(size_t)(e4 + 3) * 12];

        float hb = sbr1[lane];
        float w0l = sWr1[lane];
        unsigned long long h01 = pk2(fmaf(r0, w0l, hb), fmaf(r1, w0l, hb));
        unsigned long long h23 = pk2(fmaf(r2, w0l, hb), fmaf(r3, w0l, hb));
#pragma unroll
        for (int i = 0; i < 32; i++) {
            unsigned long long wd = dup2(sWr1[(i + 1) * 32 + lane]);
            h01 = fma2(__shfl_sync(FULL, fp01, i), wd, h01);
            h23 = fma2(__shfl_sync(FULL, fp23, i), wd, h23);
        }
        {
            float a, b;
            unpk(h01, a, b); h01 = pk2(fmaxf(a, 0.f), fmaxf(b, 0.f));
            unpk(h23, a, b); h23 = pk2(fmaxf(a, 0.f), fmaxf(b, 0.f));
        }

        unsigned long long W01[7], W23[7];
#pragma unroll
        for (int p = 0; p < 7; p++) { W01[p] = 0ull; W23[p] = 0ull; }
#pragma unroll
        for (int i = 0; i < 32; i++) {
            unsigned long long hs01 = __shfl_sync(FULL, h01, i);
            unsigned long long hs23 = __shfl_sync(FULL, h23, i);
            const float* wr = &sWr2[i * 224 + lane];
#pragma unroll
            for (int p = 0; p < 7; p++) {
                unsigned long long wd = dup2(wr[p * 32]);
                W01[p] = fma2(hs01, wd, W01[p]);
                W23[p] = fma2(hs23, wd, W23[p]);
            }
        }

#pragma unroll
        for (int pe = 0; pe < 4; pe++) {
            float wv[7];
#pragma unroll
            for (int p = 0; p < 7; p++) {
                float lo, hi;
                unpk((pe < 2) ? W01[p] : W23[p], lo, hi);
                wv[p] = (pe & 1) ? hi : lo;
            }
            int e = e4 + pe;
            int s = src[e];
            int d = dst[e];
            int p = g_pose[e];
            float f0s = f0src[(size_t)s * CC + lane];
            float m0;
            if (FIRST) {
                m0 = wv[0] * f0s;
            } else {
                const float4 ga = *(const float4*)&g_geoE[(size_t)e * 12];
                const float4 gb = *(const float4*)&g_geoE[(size_t)e * 12 + 4];
                float Y24 = g_geoE[(size_t)e * 12 + 8];
                const float* p1 = &f1src[(size_t)s * 96 + lane];
                float f1a = p1[0], f1b = p1[32], f1c = p1[64];
                const float* p2 = &f2src[(size_t)s * 160 + lane];
                float f2a = p2[0], f2b = p2[32], f2c = p2[64], f2d = p2[96], f2e = p2[128];
                float dot1 = f1a * ga.y + f1b * ga.z + f1c * ga.w;
                float dot2 = f2a * gb.x + f2b * gb.y + f2c * gb.z + f2d * gb.w + f2e * Y24;
                m0 = wv[0] * f0s + wv[1] * dot1 + wv[2] * dot2;
            }
            float* blk = &g_blk[(size_t)p * 160];
            blk[lane]      = m0;
            blk[32 + lane] = wv[3] * f0s;
            blk[96 + lane] = wv[5] * f0s;
            if (!FIRST) {
                blk[64 + lane]  = wv[4];
                blk[128 + lane] = wv[6];
            }
            float acc = 0.0f;
#pragma unroll
            for (int k = 0; k < 4; k++) {
                float mv = __shfl_sync(FULL, m0, (lane & 7) + 8 * k);
                acc = fmaf(mv, __ldg(&g_v[(size_t)d * 128 + k * 32 + lane]), acc);
            }
            acc += __shfl_xor_sync(FULL, acc, 4);
            acc += __shfl_xor_sync(FULL, acc, 2);
            acc += __shfl_xor_sync(FULL, acc, 1);
            if ((lane & 7) == 0) g_logits[p * 4 + (lane >> 3)] = acc;
        }
    }
}

// ---------------- warp-per-node: streaming softmax + aggregate + self-mix ----------------
template <bool FIRST>
__global__ void __launch_bounds__(256) agg_kernel(const float* __restrict__ Ws0,
                                                  const float* __restrict__ Ws1,
                                                  const float* __restrict__ Ws2,
                                                  const float* __restrict__ Wsk,
                                                  const float* __restrict__ f1src,
                                                  const float* __restrict__ f2src,
                                                  const float* __restrict__ f0old,
                                                  float* __restrict__ f0out,
                                                  float* __restrict__ f1out,
                                                  float* __restrict__ f2out) {
    __shared__ float sW0[1024], sW1[1024], sW2[1024], sWkm[1024];
    __shared__ float sAcc[8][320];
    int tid = threadIdx.x;
    for (int i = tid; i < 1024; i += 256) {
        sW0[i] = Ws0[i]; sW1[i] = Ws1[i]; sW2[i] = Ws2[i]; sWkm[i] = Wsk[i];
    }
    __syncthreads();

    int wid = tid >> 5, lane = tid & 31;
    int n = blockIdx.x * 8 + wid;
    int beg = g_rowptr[n], end = g_rowptr[n + 1];
    int deg = end - beg;

    float mx0 = -1e30f, mx1 = -1e30f, mx2 = -1e30f, mx3 = -1e30f;
    for (int j = lane; j < deg; j += 32) {
        float4 lg = *(const float4*)&g_logits[(beg + j) * 4];
        mx0 = fmaxf(mx0, lg.x); mx1 = fmaxf(mx1, lg.y);
        mx2 = fmaxf(mx2, lg.z); mx3 = fmaxf(mx3, lg.w);
    }
#pragma unroll
    for (int o = 16; o > 0; o >>= 1) {
        mx0 = fmaxf(mx0, __shfl_xor_sync(FULL, mx0, o));
        mx1 = fmaxf(mx1, __shfl_xor_sync(FULL, mx1, o));
        mx2 = fmaxf(mx2, __shfl_xor_sync(FULL, mx2, o));
        mx3 = fmaxf(mx3, __shfl_xor_sync(FULL, mx3, o));
    }
    float d0 = 0, d1 = 0, d2 = 0, d3 = 0;
    for (int j = lane; j < deg; j += 32) {
        float4 lg = *(const float4*)&g_logits[(beg + j) * 4];
        d0 += expf(lg.x - mx0); d1 += expf(lg.y - mx1);
        d2 += expf(lg.z - mx2); d3 += expf(lg.w - mx3);
    }
#pragma unroll
    for (int o = 16; o > 0; o >>= 1) {
        d0 += __shfl_xor_sync(FULL, d0, o);
        d1 += __shfl_xor_sync(FULL, d1, o);
        d2 += __shfl_xor_sync(FULL, d2, o);
        d3 += __shfl_xor_sync(FULL, d3, o);
    }
    int h = lane >> 3;
    float mxh  = (h == 0) ? mx0 : (h == 1) ? mx1 : (h == 2) ? mx2 : mx3;
    float invh = 1.0f / (((h == 0) ? d0 : (h == 1) ? d1 : (h == 2) ? d2 : d3) + EPSF);

    float A0 = 0, A10 = 0, A11 = 0, A12 = 0;
    float A20 = 0, A21 = 0, A22 = 0, A23 = 0, A24 = 0;
#pragma unroll 2
    for (int j = 0; j < deg; j++) {
        int p = beg + j;
        float al = expf(g_logits[p * 4 + h] - mxh) * invh;
        const float* blk = &g_blk[(size_t)p * 160];
        float m0 = blk[lane];
        float a1 = blk[32 + lane];
        float a2 = blk[96 + lane];
        const float4 ga = __ldg((const float4*)&g_geoP[(size_t)p * 12]);
        const float4 gb = __ldg((const float4*)&g_geoP[(size_t)p * 12 + 4]);
        float Y24 = __ldg(&g_geoP[(size_t)p * 12 + 8]);
        A0 = fmaf(al, m0, A0);
        float t1 = al * a1, t2 = al * a2;
        A10 = fmaf(t1, ga.y, A10); A11 = fmaf(t1, ga.z, A11); A12 = fmaf(t1, ga.w, A12);
        A20 = fmaf(t2, gb.x, A20); A21 = fmaf(t2, gb.y, A21);
        A22 = fmaf(t2, gb.z, A22); A23 = fmaf(t2, gb.w, A23); A24 = fmaf(t2, Y24, A24);
        if (!FIRST) {
            float t4 = al * blk[64 + lane];
            float t6 = al * blk[128 + lane];
            int s = __ldg(&g_srcp[p]);
            const float* p1 = &f1src[(size_t)s * 96 + lane];
            A10 = fmaf(t4, p1[0], A10); A11 = fmaf(t4, p1[32], A11); A12 = fmaf(t4, p1[64], A12);
            const float* p2 = &f2src[(size_t)s * 160 + lane];
            A20 = fmaf(t6, p2[0], A20);  A21 = fmaf(t6, p2[32], A21);
            A22 = fmaf(t6, p2[64], A22); A23 = fmaf(t6, p2[96], A23); A24 = fmaf(t6, p2[128], A24);
        }
    }

    float* sa = sAcc[wid];
    sa[lane]        = A0;
    sa[32 + lane]   = A10;
    sa[64 + lane]   = A11;
    sa[96 + lane]   = A12;
    sa[128 + lane]  = A20;
    sa[160 + lane]  = A21;
    sa[192 + lane]  = A22;
    sa[224 + lane]  = A23;
    sa[256 + lane]  = A24;
    sa[288 + lane]  = f0old[n * CC + lane];
    __syncwarp();

    float o0 = 0, o10 = 0, o11 = 0, o12 = 0;
    float o20 = 0, o21 = 0, o22 = 0, o23 = 0, o24 = 0;
#pragma unroll
    for (int c = 0; c < 32; c++) {
        float w0v = sW0[c * 32 + lane], wkv = sWkm[c * 32 + lane];
        float w1v = sW1[c * 32 + lane], w2v = sW2[c * 32 + lane];
        o0  = fmaf(sa[c], w0v, fmaf(sa[288 + c], wkv, o0));
        o10 = fmaf(sa[32 + c],  w1v, o10);
        o11 = fmaf(sa[64 + c],  w1v, o11);
        o12 = fmaf(sa[96 + c],  w1v, o12);
        o20 = fmaf(sa[128 + c], w2v, o20);
        o21 = fmaf(sa[160 + c], w2v, o21);
        o22 = fmaf(sa[192 + c], w2v, o22);
        o23 = fmaf(sa[224 + c], w2v, o23);
        o24 = fmaf(sa[256 + c], w2v, o24);
    }
    f0out[n * CC + lane] = o0;
    f1out[n * 96 + lane]       = o10;
    f1out[n * 96 + 32 + lane]  = o11;
    f1out[n * 96 + 64 + lane]  = o12;
    f2out[n * 160 + lane]        = o20;
    f2out[n * 160 + 32 + lane]   = o21;
    f2out[n * 160 + 64 + lane]   = o22;
    f2out[n * 160 + 96 + lane]   = o23;
    f2out[n * 160 + 128 + lane]  = o24;
}

// ---------------- final projection ----------------
__global__ void __launch_bounds__(256) out_kernel(const float* __restrict__ Wout,
                                                  const float* __restrict__ Wc,
                                                  const float* __restrict__ f0,
                                                  float* __restrict__ out) {
    __shared__ float sWo[1024];
    __shared__ float sWc[32 * NTT];
    int tid = threadIdx.x;
    for (int i = tid; i < 1024; i += 256) sWo[i] = Wout[i];
    for (int i = tid; i < 32 * NTT; i += 256) sWc[i] = Wc[i];
    __syncthreads();
    int lane = tid & 31;
    int n = blockIdx.x * 8 + (tid >> 5);
    float f = f0[n * CC + lane];
    float hs = 0.0f;
#pragma unroll
    for (int c = 0; c < 32; c++)
        hs = fmaf(__shfl_sync(FULL, f, c), sWo[c * 32 + lane], hs);
    out[n * CC + lane] = hs;
    float cs = 0.0f;
#pragma unroll
    for (int c = 0; c < 32; c++) {
        float hv = __shfl_sync(FULL, hs, c);
        float wc = (lane < NTT) ? sWc[c * NTT + lane] : 0.0f;
        cs = fmaf(hv, wc, cs);
    }
    if (lane < NTT) out[NN * CC + n * NTT + lane] = cs;
}

// ---------------- host ----------------
extern "C" void kernel_launch(void* const* d_in, const int* in_sizes, int n_in,
                              void* d_out, int out_size) {
    const float* pos       = (const float*)d_in[0];
    const float* node_l0   = (const float*)d_in[1];
    const float* edge_feat = (const float*)d_in[2];
    const int*   edge_src  = (const int*)d_in[3];
    const int*   edge_dst  = (const int*)d_in[4];
    const float* Wr1       = (const float*)d_in[5];
    const float* br1       = (const float*)d_in[6];
    const float* Wr2       = (const float*)d_in[7];
    const float* Wq        = (const float*)d_in[8];
    const float* Wk        = (const float*)d_in[9];
    const float* Ws0       = (const float*)d_in[10];
    const float* Ws1       = (const float*)d_in[11];
    const float* Ws2       = (const float*)d_in[12];
    const float* Wsk       = (const float*)d_in[13];
    const float* Wout      = (const float*)d_in[14];
    const float* Wc        = (const float*)d_in[15];
    float* out = (float*)d_out;

    void *pf0, *pf1, *pf2, *pM;
    cudaGetSymbolAddress(&pf0, g_f0);
    cudaGetSymbolAddress(&pf1, g_f1);
    cudaGetSymbolAddress(&pf2, g_f2);
    cudaGetSymbolAddress(&pM, g_M);
    float* f0a = (float*)pf0;
    float* f0b = f0a + (size_t)NN * CC;
    float* f1a = (float*)pf1;
    float* f1b = f1a + (size_t)NN * CC * 3;
    float* f2a = (float*)pf2;
    float* f2b = f2a + (size_t)NN * CC * 5;
    float* M0 = (float*)pM;
    float* M1 = M0 + 32 * 128;

    // launch order keeps the first edge_kernel at ncu capture index 5
    mprep_kernel<<<1, 256>>>(Wq, Wk);                               // 0
    hist_kernel<<<EE / 256, 256>>>(edge_dst);                      // 1
    scan_kernel<<<1, 1024>>>();                                    // 2
    scatter_geo_kernel<<<EE / 256, 256>>>(pos, edge_src, edge_dst);// 3

    // ---- layer 0 (f1 = f2 = 0) ----
    vn_kernel<<<NN / 8, 256>>>(M0, node_l0);                       // 4
    edge_kernel<true><<<1875, 256>>>(edge_feat, edge_src, edge_dst,// 5  <- ncu capture
                                     Wr1, br1, Wr2,
                                     node_l0, nullptr, nullptr);
    agg_kernel<true><<<NN / 8, 256>>>(Ws0, Ws1, Ws2, Wsk,
                                      nullptr, nullptr, node_l0, f0a, f1a, f2a);

    // ---- layer 1 ----
    vn_kernel<<<NN / 8, 256>>>(M1, f0a);
    edge_kernel<false><<<1875, 256>>>(edge_feat, edge_src, edge_dst,
                                      Wr1 + 33 * 32, br1 + 32, Wr2 + 32 * 224,
                                      f0a, f1a, f2a);
    agg_kernel<false><<<NN / 8, 256>>>(Ws0 + 1024, Ws1 + 1024, Ws2 + 1024, Wsk + 1024,
                                       f1a, f2a, f0a, f0b, f1b, f2b);

    out_kernel<<<NN / 8, 256>>>(Wout, Wc, f0b, out);
}

// round 9
// speedup vs baseline: 1.1171x; 1.0419x over previous
#include <cuda_runtime.h>
#include <cstdint>
#include <cstddef>

#define NN 30000
#define EE 480000
#define CC 32
#define NTT 15
#define EPSF 1e-8f

// ---------------- scratch (static device globals; no allocation) ----------------
// per-edge 64B record, indexed by ORIGINAL edge id e:
//   [0..3] logits(h0..h3)  [4]=Y10 [5]=Y11 [6]=Y12 [7]=Y20 [8]=Y21 [9]=Y22 [10]=Y23 [11]=Y24 [12]=r
__device__ float g_elog[(size_t)EE * 16];
__device__ float g_blk[(size_t)EE * 160];       // by e: m0, w3*f0s, w4, w5*f0s, w6  (5 x 32)
__device__ float g_v[(size_t)NN * 128];         // permuted per-node attention vectors
__device__ float g_M[2][32 * 128];              // fused Wq@Wk^T, float4-packed per (c,lane)
__device__ float g_f0[2][NN * CC];
__device__ float g_f1[2][NN * CC * 3];
__device__ float g_f2[2][NN * CC * 5];
__device__ int   g_cnt[NN];
__device__ int   g_rowptr[NN + 1];
__device__ int   g_cursor[NN];
__device__ int   g_eid[EE];                     // CSR position p -> original e

#define FULL 0xffffffffu

// ---------------- f32x2 packed helpers ----------------
__device__ __forceinline__ unsigned long long pk2(float lo, float hi) {
    unsigned long long r;
    asm("mov.b64 %0, {%1, %2};" : "=l"(r) : "f"(lo), "f"(hi));
    return r;
}
__device__ __forceinline__ void unpk(unsigned long long v, float& lo, float& hi) {
    asm("mov.b64 {%0, %1}, %2;" : "=f"(lo), "=f"(hi) : "l"(v));
}
__device__ __forceinline__ unsigned long long dup2(float v) {
    unsigned long long r;
    asm("mov.b64 %0, {%1, %1};" : "=l"(r) : "f"(v));
    return r;
}
__device__ __forceinline__ unsigned long long fma2(unsigned long long a, unsigned long long b,
                                                   unsigned long long c) {
    unsigned long long d;
    asm("fma.rn.f32x2 %0, %1, %2, %3;" : "=l"(d) : "l"(a), "l"(b), "l"(c));
    return d;
}

// ---------------- fused attention matrices, float4-packed ----------------
// g_M[l][(c*32+lane)*4 + k] = sum_dh Wq[c][h*8+dh]*Wk[cp][h*8+dh] / sqrt(8),
// with h = lane>>3, cp = (lane&7) + 8k
__global__ void __launch_bounds__(64) mprep_kernel(const float* __restrict__ Wq,
                                                   const float* __restrict__ Wk) {
    int t = threadIdx.x;
    int l = t >> 5, lane = t & 31;
    int h = lane >> 3;
    const float* wq = Wq + l * 1024;
    const float* wk = Wk + l * 1024;
    for (int c = 0; c < 32; c++) {
#pragma unroll
        for (int k = 0; k < 4; k++) {
            int cp = (lane & 7) + 8 * k;
            float acc = 0.0f;
#pragma unroll
            for (int dh = 0; dh < 8; dh++)
                acc = fmaf(wq[c * 32 + h * 8 + dh], wk[cp * 32 + h * 8 + dh], acc);
            g_M[l][(c * 32 + lane) * 4 + k] = acc * 0.35355339059327373f;
        }
    }
}

// ---------------- degree histogram ----------------
__global__ void __launch_bounds__(256) hist_kernel(const int* __restrict__ dst) {
    int e = blockIdx.x * 256 + threadIdx.x;
    if (e >= EE) return;
    atomicAdd(&g_cnt[dst[e]], 1);
}

// ---------------- single-block scan (re-zeroes counts for graph replay) ----------------
__global__ void __launch_bounds__(1024) scan_kernel() {
    __shared__ int ssum[1024];
    const int CH = 30;
    int t = threadIdx.x;
    int start = t * CH;
    int s = 0;
    for (int i = 0; i < CH; i++) {
        int idx = start + i;
        if (idx < NN) s += g_cnt[idx];
    }
    ssum[t] = s;
    __syncthreads();
    for (int off = 1; off < 1024; off <<= 1) {
        int v = (t >= off) ? ssum[t - off] : 0;
        __syncthreads();
        ssum[t] += v;
        __syncthreads();
    }
    int run = (t == 0) ? 0 : ssum[t - 1];
    for (int i = 0; i < CH; i++) {
        int idx = start + i;
        if (idx < NN) {
            g_rowptr[idx] = run;
            g_cursor[idx] = run;
            run += g_cnt[idx];
            g_cnt[idx] = 0;
        }
    }
    if (t == 0) g_rowptr[NN] = EE;
}

// ---------------- scatter + geometry (geo written by-e, sequential) ----------------
__global__ void __launch_bounds__(256) scatter_geo_kernel(const float* __restrict__ pos,
                                                          const int* __restrict__ src,
                                                          const int* __restrict__ dst) {
    int e = blockIdx.x * 256 + threadIdx.x;
    if (e >= EE) return;
    int s = src[e], d = dst[e];
    int p = atomicAdd(&g_cursor[d], 1);
    g_eid[p] = e;
    float rx = pos[d * 3 + 0] - pos[s * 3 + 0];
    float ry = pos[d * 3 + 1] - pos[s * 3 + 1];
    float rz = pos[d * 3 + 2] - pos[s * 3 + 2];
    float r = sqrtf(rx * rx + ry * ry + rz * rz + EPSF);
    float inv = 1.0f / r;
    float x = rx * inv, y = ry * inv, z = rz * inv;
    float* el = &g_elog[(size_t)e * 16];
    *(float4*)(el + 4) = make_float4(x, y, z, x * y);
    *(float4*)(el + 8) = make_float4(y * z, 3.0f * z * z - 1.0f, x * z, x * x - y * y);
    el[12] = r;
}

// ---------------- per-node attention vectors: v = f0 @ M (float4-packed M) ----------------
__global__ void __launch_bounds__(256) vn_kernel(const float* __restrict__ Ml,
                                                 const float* __restrict__ f0src) {
    __shared__ float sM[32 * 128];
    int tid = threadIdx.x;
    for (int i = tid; i < 32 * 128; i += 256) sM[i] = Ml[i];
    __syncthreads();
    int lane = tid & 31;
    int n = blockIdx.x * 8 + (tid >> 5);
    float f = f0src[n * CC + lane];
    float o0 = 0, o1 = 0, o2 = 0, o3 = 0;
#pragma unroll
    for (int c = 0; c < 32; c++) {
        float fc = __shfl_sync(FULL, f, c);
        float4 m = *(const float4*)&sM[(c * 32 + lane) * 4];
        o0 = fmaf(fc, m.x, o0);
        o1 = fmaf(fc, m.y, o1);
        o2 = fmaf(fc, m.z, o2);
        o3 = fmaf(fc, m.w, o3);
    }
    float* vp = &g_v[(size_t)n * 128 + lane];
    vp[0] = o0; vp[32] = o1; vp[64] = o2; vp[96] = o3;
}

// ---------------- edge kernel: 4 edges/warp, fully sequential by e ----------------
template <bool FIRST>
__global__ void __launch_bounds__(256) edge_kernel(const float* __restrict__ edge_feat,
                                                   const int* __restrict__ src,
                                                   const int* __restrict__ dst,
                                                   const float* __restrict__ Wr1,
                                                   const float* __restrict__ br1,
                                                   const float* __restrict__ Wr2,
                                                   const float* __restrict__ f0src,
                                                   const float* __restrict__ f1src,
                                                   const float* __restrict__ f2src) {
    __shared__ float sWr1[33 * 32];
    __shared__ float sbr1[32];
    __shared__ float sWr2[32 * 224];
    int tid = threadIdx.x;
    for (int i = tid; i < 33 * 32; i += 256) sWr1[i] = Wr1[i];
    if (tid < 32) sbr1[tid] = br1[tid];
    for (int i = tid; i < 32 * 224; i += 256) sWr2[i] = Wr2[i];
    __syncthreads();

    int wid = tid >> 5, lane = tid & 31;
    int wstride = gridDim.x * 8;

    for (int g = blockIdx.x * 8 + wid; g < EE / 4; g += wstride) {
        int e4 = g * 4;

        float feat0 = edge_feat[(size_t)(e4 + 0) * CC + lane];
        float feat1 = edge_feat[(size_t)(e4 + 1) * CC + lane];
        float feat2 = edge_feat[(size_t)(e4 + 2) * CC + lane];
        float feat3 = edge_feat[(size_t)(e4 + 3) * CC + lane];
        unsigned long long fp01 = pk2(feat0, feat1);
        unsigned long long fp23 = pk2(feat2, feat3);
        float r0 = g_elog[(size_t)(e4 + 0) * 16 + 12];
        float r1 = g_elog[(size_t)(e4 + 1) * 16 + 12];
        float r2 = g_elog[(size_t)(e4 + 2) * 16 + 12];
        float r3 = g_elog[(size_t)(e4 + 3) * 16 + 12];

        float hb = sbr1[lane];
        float w0l = sWr1[lane];
        unsigned long long h01 = pk2(fmaf(r0, w0l, hb), fmaf(r1, w0l, hb));
        unsigned long long h23 = pk2(fmaf(r2, w0l, hb), fmaf(r3, w0l, hb));
#pragma unroll
        for (int i = 0; i < 32; i++) {
            unsigned long long wd = dup2(sWr1[(i + 1) * 32 + lane]);
            h01 = fma2(__shfl_sync(FULL, fp01, i), wd, h01);
            h23 = fma2(__shfl_sync(FULL, fp23, i), wd, h23);
        }
        {
            float a, b;
            unpk(h01, a, b); h01 = pk2(fmaxf(a, 0.f), fmaxf(b, 0.f));
            unpk(h23, a, b); h23 = pk2(fmaxf(a, 0.f), fmaxf(b, 0.f));
        }

        unsigned long long W01[7], W23[7];
#pragma unroll
        for (int p = 0; p < 7; p++) { W01[p] = 0ull; W23[p] = 0ull; }
#pragma unroll
        for (int i = 0; i < 32; i++) {
            unsigned long long hs01 = __shfl_sync(FULL, h01, i);
            unsigned long long hs23 = __shfl_sync(FULL, h23, i);
            const float* wr = &sWr2[i * 224 + lane];
#pragma unroll
            for (int p = 0; p < 7; p++) {
                unsigned long long wd = dup2(wr[p * 32]);
                W01[p] = fma2(hs01, wd, W01[p]);
                W23[p] = fma2(hs23, wd, W23[p]);
            }
        }

#pragma unroll
        for (int pe = 0; pe < 4; pe++) {
            float wv[7];
#pragma unroll
            for (int p = 0; p < 7; p++) {
                float lo, hi;
                unpk((pe < 2) ? W01[p] : W23[p], lo, hi);
                wv[p] = (pe & 1) ? hi : lo;
            }
            int e = e4 + pe;
            int s = src[e];
            int d = dst[e];
            float f0s = f0src[(size_t)s * CC + lane];
            float m0;
            if (FIRST) {
                m0 = wv[0] * f0s;
            } else {
                const float4 ga = *(const float4*)&g_elog[(size_t)e * 16 + 4];
                const float4 gb = *(const float4*)&g_elog[(size_t)e * 16 + 8];
                const float* p1 = &f1src[(size_t)s * 96 + lane];
                float f1a = p1[0], f1b = p1[32], f1c = p1[64];
                const float* p2 = &f2src[(size_t)s * 160 + lane];
                float f2a = p2[0], f2b = p2[32], f2c = p2[64], f2d = p2[96], f2e = p2[128];
                float dot1 = f1a * ga.x + f1b * ga.y + f1c * ga.z;
                float dot2 = f2a * ga.w + f2b * gb.x + f2c * gb.y + f2d * gb.z + f2e * gb.w;
                m0 = wv[0] * f0s + wv[1] * dot1 + wv[2] * dot2;
            }
            float* blk = &g_blk[(size_t)e * 160];
            blk[lane]      = m0;
            blk[32 + lane] = wv[3] * f0s;
            blk[96 + lane] = wv[5] * f0s;
            if (!FIRST) {
                blk[64 + lane]  = wv[4];
                blk[128 + lane] = wv[6];
            }
            float acc = 0.0f;
#pragma unroll
            for (int k = 0; k < 4; k++) {
                float mv = __shfl_sync(FULL, m0, (lane & 7) + 8 * k);
                acc = fmaf(mv, __ldg(&g_v[(size_t)d * 128 + k * 32 + lane]), acc);
            }
            acc += __shfl_xor_sync(FULL, acc, 4);
            acc += __shfl_xor_sync(FULL, acc, 2);
            acc += __shfl_xor_sync(FULL, acc, 1);
            if ((lane & 7) == 0) g_elog[(size_t)e * 16 + (lane >> 3)] = acc;
        }
    }
}

// ---------------- warp-per-node: cached softmax + aggregate + self-mix ----------------
template <bool FIRST>
__global__ void __launch_bounds__(256) agg_kernel(const float* __restrict__ Ws0,
                                                  const float* __restrict__ Ws1,
                                                  const float* __restrict__ Ws2,
                                                  const float* __restrict__ Wsk,
                                                  const int* __restrict__ srcArr,
                                                  const float* __restrict__ f1src,
                                                  const float* __restrict__ f2src,
                                                  const float* __restrict__ f0old,
                                                  float* __restrict__ f0out,
                                                  float* __restrict__ f1out,
                                                  float* __restrict__ f2out) {
    __shared__ float sW0[1024], sW1[1024], sW2[1024], sWkm[1024];
    __shared__ float sAcc[8][320];
    __shared__ float sAl[8][256];     // alpha4 per cached edge (<=64)
    __shared__ int   sEid[8][64];
    int tid = threadIdx.x;
    for (int i = tid; i < 1024; i += 256) {
        sW0[i] = Ws0[i]; sW1[i] = Ws1[i]; sW2[i] = Ws2[i]; sWkm[i] = Wsk[i];
    }
    __syncthreads();

    int wid = tid >> 5, lane = tid & 31;
    int n = blockIdx.x * 8 + wid;
    int beg = g_rowptr[n], end = g_rowptr[n + 1];
    int deg = end - beg;

    // pass 1: load logits once (cache for deg<=64), per-head max
    float4 rlg0 = make_float4(0, 0, 0, 0), rlg1 = make_float4(0, 0, 0, 0);
    float mx0 = -1e30f, mx1 = -1e30f, mx2 = -1e30f, mx3 = -1e30f;
    for (int j = lane; j < deg; j += 32) {
        int e = g_eid[beg + j];
        float4 lg = *(const float4*)&g_elog[(size_t)e * 16];
        if (j < 64) {
            sEid[wid][j] = e;
            if (j < 32) rlg0 = lg; else rlg1 = lg;
        }
        mx0 = fmaxf(mx0, lg.x); mx1 = fmaxf(mx1, lg.y);
        mx2 = fmaxf(mx2, lg.z); mx3 = fmaxf(mx3, lg.w);
    }
#pragma unroll
    for (int o = 16; o > 0; o >>= 1) {
        mx0 = fmaxf(mx0, __shfl_xor_sync(FULL, mx0, o));
        mx1 = fmaxf(mx1, __shfl_xor_sync(FULL, mx1, o));
        mx2 = fmaxf(mx2, __shfl_xor_sync(FULL, mx2, o));
        mx3 = fmaxf(mx3, __shfl_xor_sync(FULL, mx3, o));
    }
    // pass 2: denominators from cached registers (global reload only if deg>64)
    float d0 = 0, d1 = 0, d2 = 0, d3 = 0;
    for (int j = lane; j < deg; j += 32) {
        float4 lg;
        if (j < 32) lg = rlg0;
        else if (j < 64) lg = rlg1;
        else lg = *(const float4*)&g_elog[(size_t)g_eid[beg + j] * 16];
        d0 += expf(lg.x - mx0); d1 += expf(lg.y - mx1);
        d2 += expf(lg.z - mx2); d3 += expf(lg.w - mx3);
    }
#pragma unroll
    for (int o = 16; o > 0; o >>= 1) {
        d0 += __shfl_xor_sync(FULL, d0, o);
        d1 += __shfl_xor_sync(FULL, d1, o);
        d2 += __shfl_xor_sync(FULL, d2, o);
        d3 += __shfl_xor_sync(FULL, d3, o);
    }
    float i0 = 1.0f / (d0 + EPSF), i1 = 1.0f / (d1 + EPSF);
    float i2 = 1.0f / (d2 + EPSF), i3 = 1.0f / (d3 + EPSF);
    // write cached alphas to smem
    for (int j = lane; j < deg && j < 64; j += 32) {
        float4 lg = (j < 32) ? rlg0 : rlg1;
        float4 al = make_float4(expf(lg.x - mx0) * i0, expf(lg.y - mx1) * i1,
                                expf(lg.z - mx2) * i2, expf(lg.w - mx3) * i3);
        *(float4*)&sAl[wid][j * 4] = al;
    }
    __syncwarp();

    int h = lane >> 3;
    float mxh  = (h == 0) ? mx0 : (h == 1) ? mx1 : (h == 2) ? mx2 : mx3;
    float invh = (h == 0) ? i0 : (h == 1) ? i1 : (h == 2) ? i2 : i3;

    float A0 = 0, A10 = 0, A11 = 0, A12 = 0;
    float A20 = 0, A21 = 0, A22 = 0, A23 = 0, A24 = 0;
#pragma unroll 2
    for (int j = 0; j < deg; j++) {
        int e;
        float al;
        if (j < 64) {
            e = sEid[wid][j];
            al = sAl[wid][j * 4 + h];
        } else {
            e = g_eid[beg + j];
            al = expf(g_elog[(size_t)e * 16 + h] - mxh) * invh;
        }
        const float* blk = &g_blk[(size_t)e * 160];
        float m0 = blk[lane];
        float a1 = blk[32 + lane];
        float a2 = blk[96 + lane];
        const float4 ga = __ldg((const float4*)&g_elog[(size_t)e * 16 + 4]);
        const float4 gb = __ldg((const float4*)&g_elog[(size_t)e * 16 + 8]);
        A0 = fmaf(al, m0, A0);
        float t1 = al * a1, t2 = al * a2;
        A10 = fmaf(t1, ga.x, A10); A11 = fmaf(t1, ga.y, A11); A12 = fmaf(t1, ga.z, A12);
        A20 = fmaf(t2, ga.w, A20); A21 = fmaf(t2, gb.x, A21);
        A22 = fmaf(t2, gb.y, A22); A23 = fmaf(t2, gb.z, A23); A24 = fmaf(t2, gb.w, A24);
        if (!FIRST) {
            float t4 = al * blk[64 + lane];
            float t6 = al * blk[128 + lane];
            int s = __ldg(&srcArr[e]);
            const float* p1 = &f1src[(size_t)s * 96 + lane];
            A10 = fmaf(t4, p1[0], A10); A11 = fmaf(t4, p1[32], A11); A12 = fmaf(t4, p1[64], A12);
            const float* p2 = &f2src[(size_t)s * 160 + lane];
            A20 = fmaf(t6, p2[0], A20);  A21 = fmaf(t6, p2[32], A21);
            A22 = fmaf(t6, p2[64], A22); A23 = fmaf(t6, p2[96], A23); A24 = fmaf(t6, p2[128], A24);
        }
    }

    float* sa = sAcc[wid];
    sa[lane]        = A0;
    sa[32 + lane]   = A10;
    sa[64 + lane]   = A11;
    sa[96 + lane]   = A12;
    sa[128 + lane]  = A20;
    sa[160 + lane]  = A21;
    sa[192 + lane]  = A22;
    sa[224 + lane]  = A23;
    sa[256 + lane]  = A24;
    sa[288 + lane]  = f0old[n * CC + lane];
    __syncwarp();

    float o0 = 0, o10 = 0, o11 = 0, o12 = 0;
    float o20 = 0, o21 = 0, o22 = 0, o23 = 0, o24 = 0;
#pragma unroll
    for (int c = 0; c < 32; c++) {
        float w0v = sW0[c * 32 + lane], wkv = sWkm[c * 32 + lane];
        float w1v = sW1[c * 32 + lane], w2v = sW2[c * 32 + lane];
        o0  = fmaf(sa[c], w0v, fmaf(sa[288 + c], wkv, o0));
        o10 = fmaf(sa[32 + c],  w1v, o10);
        o11 = fmaf(sa[64 + c],  w1v, o11);
        o12 = fmaf(sa[96 + c],  w1v, o12);
        o20 = fmaf(sa[128 + c], w2v, o20);
        o21 = fmaf(sa[160 + c], w2v, o21);
        o22 = fmaf(sa[192 + c], w2v, o22);
        o23 = fmaf(sa[224 + c], w2v, o23);
        o24 = fmaf(sa[256 + c], w2v, o24);
    }
    f0out[n * CC + lane] = o0;
    f1out[n * 96 + lane]       = o10;
    f1out[n * 96 + 32 + lane]  = o11;
    f1out[n * 96 + 64 + lane]  = o12;
    f2out[n * 160 + lane]        = o20;
    f2out[n * 160 + 32 + lane]   = o21;
    f2out[n * 160 + 64 + lane]   = o22;
    f2out[n * 160 + 96 + lane]   = o23;
    f2out[n * 160 + 128 + lane]  = o24;
}

// ---------------- final projection ----------------
__global__ void __launch_bounds__(256) out_kernel(const float* __restrict__ Wout,
                                                  const float* __restrict__ Wc,
                                                  const float* __restrict__ f0,
                                                  float* __restrict__ out) {
    __shared__ float sWo[1024];
    __shared__ float sWc[32 * NTT];
    int tid = threadIdx.x;
    for (int i = tid; i < 1024; i += 256) sWo[i] = Wout[i];
    for (int i = tid; i < 32 * NTT; i += 256) sWc[i] = Wc[i];
    __syncthreads();
    int lane = tid & 31;
    int n = blockIdx.x * 8 + (tid >> 5);
    float f = f0[n * CC + lane];
    float hs = 0.0f;
#pragma unroll
    for (int c = 0; c < 32; c++)
        hs = fmaf(__shfl_sync(FULL, f, c), sWo[c * 32 + lane], hs);
    out[n * CC + lane] = hs;
    float cs = 0.0f;
#pragma unroll
    for (int c = 0; c < 32; c++) {
        float hv = __shfl_sync(FULL, hs, c);
        float wc = (lane < NTT) ? sWc[c * NTT + lane] : 0.0f;
        cs = fmaf(hv, wc, cs);
    }
    if (lane < NTT) out[NN * CC + n * NTT + lane] = cs;
}

// ---------------- host ----------------
extern "C" void kernel_launch(void* const* d_in, const int* in_sizes, int n_in,
                              void* d_out, int out_size) {
    const float* pos       = (const float*)d_in[0];
    const float* node_l0   = (const float*)d_in[1];
    const float* edge_feat = (const float*)d_in[2];
    const int*   edge_src  = (const int*)d_in[3];
    const int*   edge_dst  = (const int*)d_in[4];
    const float* Wr1       = (const float*)d_in[5];
    const float* br1       = (const float*)d_in[6];
    const float* Wr2       = (const float*)d_in[7];
    const float* Wq        = (const float*)d_in[8];
    const float* Wk        = (const float*)d_in[9];
    const float* Ws0       = (const float*)d_in[10];
    const float* Ws1       = (const float*)d_in[11];
    const float* Ws2       = (const float*)d_in[12];
    const float* Wsk       = (const float*)d_in[13];
    const float* Wout      = (const float*)d_in[14];
    const float* Wc        = (const float*)d_in[15];
    float* out = (float*)d_out;

    void *pf0, *pf1, *pf2, *pM;
    cudaGetSymbolAddress(&pf0, g_f0);
    cudaGetSymbolAddress(&pf1, g_f1);
    cudaGetSymbolAddress(&pf2, g_f2);
    cudaGetSymbolAddress(&pM, g_M);
    float* f0a = (float*)pf0;
    float* f0b = f0a + (size_t)NN * CC;
    float* f1a = (float*)pf1;
    float* f1b = f1a + (size_t)NN * CC * 3;
    float* f2a = (float*)pf2;
    float* f2b = f2a + (size_t)NN * CC * 5;
    float* M0 = (float*)pM;
    float* M1 = M0 + 32 * 128;

    mprep_kernel<<<1, 64>>>(Wq, Wk);
    hist_kernel<<<EE / 256, 256>>>(edge_dst);
    scan_kernel<<<1, 1024>>>();
    scatter_geo_kernel<<<EE / 256, 256>>>(pos, edge_src, edge_dst);

    // ---- layer 0 (f1 = f2 = 0) ----
    vn_kernel<<<NN / 8, 256>>>(M0, node_l0);
    edge_kernel<true><<<1875, 256>>>(edge_feat, edge_src, edge_dst,
                                     Wr1, br1, Wr2,
                                     node_l0, nullptr, nullptr);
    agg_kernel<true><<<NN / 8, 256>>>(Ws0, Ws1, Ws2, Wsk, edge_src,
                                      nullptr, nullptr, node_l0, f0a, f1a, f2a);

    // ---- layer 1 ----
    vn_kernel<<<NN / 8, 256>>>(M1, f0a);
    edge_kernel<false><<<1875, 256>>>(edge_feat, edge_src, edge_dst,
                                      Wr1 + 33 * 32, br1 + 32, Wr2 + 32 * 224,
                                      f0a, f1a, f2a);
    agg_kernel<false><<<NN / 8, 256>>>(Ws0 + 1024, Ws1 + 1024, Ws2 + 1024, Wsk + 1024,
                                       edge_src, f1a, f2a, f0a, f0b, f1b, f2b);

    out_kernel<<<NN / 8, 256>>>(Wout, Wc, f0b, out);
}

// round 10
// speedup vs baseline: 1.3693x; 1.2258x over previous
#include <cuda_runtime.h>
#include <cstdint>
#include <cstddef>

#define NN 30000
#define EE 480000
#define CC 32
#define NTT 15
#define EPSF 1e-8f

// ---------------- scratch (static device globals; no allocation) ----------------
__device__ float g_geoP[(size_t)EE * 12];  // by CSR pos p: [0..3]=(r,Y10,Y11,Y12) [4..7]=Y20..Y23 [8]=Y24
__device__ float g_v[(size_t)NN * 128];    // permuted per-node attention vectors
__device__ float g_M[2][32 * 128];         // fused Wq@Wk^T, float4-packed per (c,lane)
__device__ float g_agg[(size_t)NN * 288];  // normalized aggregates: 9 x 32 per node
__device__ float g_f0[2][NN * CC];
__device__ float g_f1[2][NN * CC * 3];
__device__ float g_f2[2][NN * CC * 5];
__device__ int   g_cnt[NN];
__device__ int   g_rowptr[NN + 1];
__device__ int   g_cursor[NN];
__device__ int   g_eid[EE];                // p -> original edge e (for edge_feat)
__device__ int   g_srcp[EE];               // p -> src node

#define FULL 0xffffffffu

// ---------------- f32x2 packed helpers ----------------
__device__ __forceinline__ unsigned long long pk2(float lo, float hi) {
    unsigned long long r;
    asm("mov.b64 %0, {%1, %2};" : "=l"(r) : "f"(lo), "f"(hi));
    return r;
}
__device__ __forceinline__ void unpk(unsigned long long v, float& lo, float& hi) {
    asm("mov.b64 {%0, %1}, %2;" : "=f"(lo), "=f"(hi) : "l"(v));
}
__device__ __forceinline__ unsigned long long dup2(float v) {
    unsigned long long r;
    asm("mov.b64 %0, {%1, %1};" : "=l"(r) : "f"(v));
    return r;
}
__device__ __forceinline__ unsigned long long fma2(unsigned long long a, unsigned long long b,
                                                   unsigned long long c) {
    unsigned long long d;
    asm("fma.rn.f32x2 %0, %1, %2, %3;" : "=l"(d) : "l"(a), "l"(b), "l"(c));
    return d;
}

// ---------------- fused attention matrices, float4-packed ----------------
__global__ void __launch_bounds__(64) mprep_kernel(const float* __restrict__ Wq,
                                                   const float* __restrict__ Wk) {
    int t = threadIdx.x;
    int l = t >> 5, lane = t & 31;
    int h = lane >> 3;
    const float* wq = Wq + l * 1024;
    const float* wk = Wk + l * 1024;
    for (int c = 0; c < 32; c++) {
#pragma unroll
        for (int k = 0; k < 4; k++) {
            int cp = (lane & 7) + 8 * k;
            float acc = 0.0f;
#pragma unroll
            for (int dh = 0; dh < 8; dh++)
                acc = fmaf(wq[c * 32 + h * 8 + dh], wk[cp * 32 + h * 8 + dh], acc);
            g_M[l][(c * 32 + lane) * 4 + k] = acc * 0.35355339059327373f;
        }
    }
}

// ---------------- degree histogram ----------------
__global__ void __launch_bounds__(256) hist_kernel(const int* __restrict__ dst) {
    int e = blockIdx.x * 256 + threadIdx.x;
    if (e >= EE) return;
    atomicAdd(&g_cnt[dst[e]], 1);
}

// ---------------- single-block scan (re-zeroes counts for graph replay) ----------------
__global__ void __launch_bounds__(1024) scan_kernel() {
    __shared__ int ssum[1024];
    const int CH = 30;
    int t = threadIdx.x;
    int start = t * CH;
    int s = 0;
    for (int i = 0; i < CH; i++) {
        int idx = start + i;
        if (idx < NN) s += g_cnt[idx];
    }
    ssum[t] = s;
    __syncthreads();
    for (int off = 1; off < 1024; off <<= 1) {
        int v = (t >= off) ? ssum[t - off] : 0;
        __syncthreads();
        ssum[t] += v;
        __syncthreads();
    }
    int run = (t == 0) ? 0 : ssum[t - 1];
    for (int i = 0; i < CH; i++) {
        int idx = start + i;
        if (idx < NN) {
            g_rowptr[idx] = run;
            g_cursor[idx] = run;
            run += g_cnt[idx];
            g_cnt[idx] = 0;
        }
    }
    if (t == 0) g_rowptr[NN] = EE;
}

// ---------------- scatter + geometry into CSR order ----------------
__global__ void __launch_bounds__(256) scatter_geo_kernel(const float* __restrict__ pos,
                                                          const int* __restrict__ src,
                                                          const int* __restrict__ dst) {
    int e = blockIdx.x * 256 + threadIdx.x;
    if (e >= EE) return;
    int s = src[e], d = dst[e];
    int p = atomicAdd(&g_cursor[d], 1);
    g_eid[p] = e;
    g_srcp[p] = s;
    float rx = pos[d * 3 + 0] - pos[s * 3 + 0];
    float ry = pos[d * 3 + 1] - pos[s * 3 + 1];
    float rz = pos[d * 3 + 2] - pos[s * 3 + 2];
    float r = sqrtf(rx * rx + ry * ry + rz * rz + EPSF);
    float inv = 1.0f / r;
    float x = rx * inv, y = ry * inv, z = rz * inv;
    float* gp = &g_geoP[(size_t)p * 12];
    *(float4*)(gp)     = make_float4(r, x, y, z);
    *(float4*)(gp + 4) = make_float4(x * y, y * z, 3.0f * z * z - 1.0f, x * z);
    gp[8] = x * x - y * y;
}

// ---------------- per-node attention vectors: v = f0 @ M ----------------
__global__ void __launch_bounds__(256) vn_kernel(const float* __restrict__ Ml,
                                                 const float* __restrict__ f0src) {
    __shared__ float sM[32 * 128];
    int tid = threadIdx.x;
    for (int i = tid; i < 32 * 128; i += 256) sM[i] = Ml[i];
    __syncthreads();
    int lane = tid & 31;
    int n = blockIdx.x * 8 + (tid >> 5);
    float f = f0src[n * CC + lane];
    float o0 = 0, o1 = 0, o2 = 0, o3 = 0;
#pragma unroll
    for (int c = 0; c < 32; c++) {
        float fc = __shfl_sync(FULL, f, c);
        float4 m = *(const float4*)&sM[(c * 32 + lane) * 4];
        o0 = fmaf(fc, m.x, o0);
        o1 = fmaf(fc, m.y, o1);
        o2 = fmaf(fc, m.z, o2);
        o3 = fmaf(fc, m.w, o3);
    }
    float* vp = &g_v[(size_t)n * 128 + lane];
    vp[0] = o0; vp[32] = o1; vp[64] = o2; vp[96] = o3;
}

// ---------------- FUSED: warp-per-node edge MLP + message + online softmax aggregate ----------------
template <bool FIRST>
__global__ void __launch_bounds__(256) fused_kernel(const float* __restrict__ edge_feat,
                                                    const float* __restrict__ Wr1,
                                                    const float* __restrict__ br1,
                                                    const float* __restrict__ Wr2,
                                                    const float* __restrict__ f0src,
                                                    const float* __restrict__ f1src,
                                                    const float* __restrict__ f2src) {
    __shared__ float sWr1[33 * 32];
    __shared__ float sbr1[32];
    __shared__ float sWr2[32 * 224];
    int tid = threadIdx.x;
    for (int i = tid; i < 33 * 32; i += 256) sWr1[i] = Wr1[i];
    if (tid < 32) sbr1[tid] = br1[tid];
    for (int i = tid; i < 32 * 224; i += 256) sWr2[i] = Wr2[i];
    __syncthreads();

    int wid = tid >> 5, lane = tid & 31;
    int nwarps = gridDim.x * 8;

    for (int n = blockIdx.x * 8 + wid; n < NN; n += nwarps) {
        int beg = g_rowptr[n];
        int deg = g_rowptr[n + 1] - beg;

        const float* vp = &g_v[(size_t)n * 128 + lane];
        float v0 = vp[0], v1 = vp[32], v2 = vp[64], v3 = vp[96];

        float mx = -1e30f, den = 0.0f;
        float A0 = 0, A10 = 0, A11 = 0, A12 = 0;
        float A20 = 0, A21 = 0, A22 = 0, A23 = 0, A24 = 0;

        for (int j0 = 0; j0 < deg; j0 += 4) {
            int cnt = deg - j0; if (cnt > 4) cnt = 4;
            int p0 = beg + j0;
            int p1 = beg + j0 + ((1 < cnt) ? 1 : 0);
            int p2 = beg + j0 + ((2 < cnt) ? 2 : 0);
            int p3 = beg + j0 + ((3 < cnt) ? 3 : 0);
            int e0 = g_eid[p0], e1 = g_eid[p1], e2 = g_eid[p2], e3 = g_eid[p3];

            unsigned long long fp01 = pk2(edge_feat[(size_t)e0 * CC + lane],
                                          edge_feat[(size_t)e1 * CC + lane]);
            unsigned long long fp23 = pk2(edge_feat[(size_t)e2 * CC + lane],
                                          edge_feat[(size_t)e3 * CC + lane]);
            float r0 = g_geoP[(size_t)p0 * 12];
            float r1 = g_geoP[(size_t)p1 * 12];
            float r2 = g_geoP[(size_t)p2 * 12];
            float r3 = g_geoP[(size_t)p3 * 12];

            // hidden = relu([r,feat] @ Wr1 + b), 4 edges in two f32x2 lanes
            float hb = sbr1[lane];
            float w0l = sWr1[lane];
            unsigned long long h01 = pk2(fmaf(r0, w0l, hb), fmaf(r1, w0l, hb));
            unsigned long long h23 = pk2(fmaf(r2, w0l, hb), fmaf(r3, w0l, hb));
#pragma unroll
            for (int i = 0; i < 32; i++) {
                unsigned long long wd = dup2(sWr1[(i + 1) * 32 + lane]);
                h01 = fma2(__shfl_sync(FULL, fp01, i), wd, h01);
                h23 = fma2(__shfl_sync(FULL, fp23, i), wd, h23);
            }
            {
                float a, b;
                unpk(h01, a, b); h01 = pk2(fmaxf(a, 0.f), fmaxf(b, 0.f));
                unpk(h23, a, b); h23 = pk2(fmaxf(a, 0.f), fmaxf(b, 0.f));
            }

            // w = hidden @ Wr2 : 7 outputs/lane x 4 edges
            unsigned long long W01[7], W23[7];
#pragma unroll
            for (int p = 0; p < 7; p++) { W01[p] = 0ull; W23[p] = 0ull; }
#pragma unroll
            for (int i = 0; i < 32; i++) {
                unsigned long long hs01 = __shfl_sync(FULL, h01, i);
                unsigned long long hs23 = __shfl_sync(FULL, h23, i);
                const float* wr = &sWr2[i * 224 + lane];
#pragma unroll
                for (int p = 0; p < 7; p++) {
                    unsigned long long wd = dup2(wr[p * 32]);
                    W01[p] = fma2(hs01, wd, W01[p]);
                    W23[p] = fma2(hs23, wd, W23[p]);
                }
            }

            // per-edge: message, logit, online-softmax accumulate (cnt is warp-uniform)
#pragma unroll
            for (int pe = 0; pe < 4; pe++) {
                if (pe < cnt) {
                    float wv[7];
#pragma unroll
                    for (int p = 0; p < 7; p++) {
                        float lo, hi;
                        unpk((pe < 2) ? W01[p] : W23[p], lo, hi);
                        wv[p] = (pe & 1) ? hi : lo;
                    }
                    int p = beg + j0 + pe;
                    int s = g_srcp[p];
                    float f0s = f0src[(size_t)s * CC + lane];
                    const float4 ga = *(const float4*)&g_geoP[(size_t)p * 12];      // r,Y10,Y11,Y12
                    const float4 gb = *(const float4*)&g_geoP[(size_t)p * 12 + 4];  // Y20..Y23
                    float Y24 = g_geoP[(size_t)p * 12 + 8];

                    float b1 = wv[3] * f0s;
                    float b2 = wv[5] * f0s;
                    float m0;
                    float f1a = 0, f1b = 0, f1c = 0;
                    float f2a = 0, f2b = 0, f2c = 0, f2d = 0, f2e = 0;
                    if (FIRST) {
                        m0 = wv[0] * f0s;
                    } else {
                        const float* q1 = &f1src[(size_t)s * 96 + lane];
                        f1a = q1[0]; f1b = q1[32]; f1c = q1[64];
                        const float* q2 = &f2src[(size_t)s * 160 + lane];
                        f2a = q2[0]; f2b = q2[32]; f2c = q2[64]; f2d = q2[96]; f2e = q2[128];
                        float dot1 = f1a * ga.y + f1b * ga.z + f1c * ga.w;
                        float dot2 = f2a * gb.x + f2b * gb.y + f2c * gb.z + f2d * gb.w + f2e * Y24;
                        m0 = wv[0] * f0s + wv[1] * dot1 + wv[2] * dot2;
                    }

                    // logit for this lane's head (8-lane group reduce)
                    float acc = 0.0f;
                    acc = fmaf(__shfl_sync(FULL, m0, (lane & 7)),      v0, acc);
                    acc = fmaf(__shfl_sync(FULL, m0, (lane & 7) + 8),  v1, acc);
                    acc = fmaf(__shfl_sync(FULL, m0, (lane & 7) + 16), v2, acc);
                    acc = fmaf(__shfl_sync(FULL, m0, (lane & 7) + 24), v3, acc);
                    acc += __shfl_xor_sync(FULL, acc, 4);
                    acc += __shfl_xor_sync(FULL, acc, 2);
                    acc += __shfl_xor_sync(FULL, acc, 1);
                    float lg = acc;

                    // online softmax update (per-lane, head = lane>>3)
                    float nmx = fmaxf(mx, lg);
                    float sc = expf(mx - nmx);
                    float w = expf(lg - nmx);
                    mx = nmx;
                    den = den * sc + w;
                    float t1 = w * b1, t2 = w * b2;
                    A0 = A0 * sc + w * m0;
                    if (FIRST) {
                        A10 = fmaf(t1, ga.y, A10 * sc);
                        A11 = fmaf(t1, ga.z, A11 * sc);
                        A12 = fmaf(t1, ga.w, A12 * sc);
                        A20 = fmaf(t2, gb.x, A20 * sc);
                        A21 = fmaf(t2, gb.y, A21 * sc);
                        A22 = fmaf(t2, gb.z, A22 * sc);
                        A23 = fmaf(t2, gb.w, A23 * sc);
                        A24 = fmaf(t2, Y24,  A24 * sc);
                    } else {
                        float t4 = w * wv[4], t6 = w * wv[6];
                        A10 = fmaf(t1, ga.y, fmaf(t4, f1a, A10 * sc));
                        A11 = fmaf(t1, ga.z, fmaf(t4, f1b, A11 * sc));
                        A12 = fmaf(t1, ga.w, fmaf(t4, f1c, A12 * sc));
                        A20 = fmaf(t2, gb.x, fmaf(t6, f2a, A20 * sc));
                        A21 = fmaf(t2, gb.y, fmaf(t6, f2b, A21 * sc));
                        A22 = fmaf(t2, gb.z, fmaf(t6, f2c, A22 * sc));
                        A23 = fmaf(t2, gb.w, fmaf(t6, f2d, A23 * sc));
                        A24 = fmaf(t2, Y24,  fmaf(t6, f2e, A24 * sc));
                    }
                }
            }
        }

        float invd = 1.0f / (den + EPSF);
        float* ag = &g_agg[(size_t)n * 288];
        ag[lane]        = A0 * invd;
        ag[32 + lane]   = A10 * invd;
        ag[64 + lane]   = A11 * invd;
        ag[96 + lane]   = A12 * invd;
        ag[128 + lane]  = A20 * invd;
        ag[160 + lane]  = A21 * invd;
        ag[192 + lane]  = A22 * invd;
        ag[224 + lane]  = A23 * invd;
        ag[256 + lane]  = A24 * invd;
    }
}

// ---------------- self-interaction + skip: streaming GEMVs ----------------
__global__ void __launch_bounds__(256) selfmix_kernel(const float* __restrict__ Ws0,
                                                      const float* __restrict__ Ws1,
                                                      const float* __restrict__ Ws2,
                                                      const float* __restrict__ Wsk,
                                                      const float* __restrict__ f0old,
                                                      float* __restrict__ f0out,
                                                      float* __restrict__ f1out,
                                                      float* __restrict__ f2out) {
    __shared__ float sW0[1024], sW1[1024], sW2[1024], sWkm[1024];
    __shared__ float sAcc[8][320];
    int tid = threadIdx.x;
    for (int i = tid; i < 1024; i += 256) {
        sW0[i] = Ws0[i]; sW1[i] = Ws1[i]; sW2[i] = Ws2[i]; sWkm[i] = Wsk[i];
    }
    __syncthreads();

    int wid = tid >> 5, lane = tid & 31;
    int n = blockIdx.x * 8 + wid;
    float* sa = sAcc[wid];
    const float* ag = &g_agg[(size_t)n * 288];
#pragma unroll
    for (int q = 0; q < 9; q++) sa[q * 32 + lane] = ag[q * 32 + lane];
    sa[288 + lane] = f0old[n * CC + lane];
    __syncwarp();

    float o0 = 0, o10 = 0, o11 = 0, o12 = 0;
    float o20 = 0, o21 = 0, o22 = 0, o23 = 0, o24 = 0;
#pragma unroll
    for (int c = 0; c < 32; c++) {
        float w0v = sW0[c * 32 + lane], wkv = sWkm[c * 32 + lane];
        float w1v = sW1[c * 32 + lane], w2v = sW2[c * 32 + lane];
        o0  = fmaf(sa[c], w0v, fmaf(sa[288 + c], wkv, o0));
        o10 = fmaf(sa[32 + c],  w1v, o10);
        o11 = fmaf(sa[64 + c],  w1v, o11);
        o12 = fmaf(sa[96 + c],  w1v, o12);
        o20 = fmaf(sa[128 + c], w2v, o20);
        o21 = fmaf(sa[160 + c], w2v, o21);
        o22 = fmaf(sa[192 + c], w2v, o22);
        o23 = fmaf(sa[224 + c], w2v, o23);
        o24 = fmaf(sa[256 + c], w2v, o24);
    }
    f0out[n * CC + lane] = o0;
    f1out[n * 96 + lane]       = o10;
    f1out[n * 96 + 32 + lane]  = o11;
    f1out[n * 96 + 64 + lane]  = o12;
    f2out[n * 160 + lane]        = o20;
    f2out[n * 160 + 32 + lane]   = o21;
    f2out[n * 160 + 64 + lane]   = o22;
    f2out[n * 160 + 96 + lane]   = o23;
    f2out[n * 160 + 128 + lane]  = o24;
}

// ---------------- final projection ----------------
__global__ void __launch_bounds__(256) out_kernel(const float* __restrict__ Wout,
                                                  const float* __restrict__ Wc,
                                                  const float* __restrict__ f0,
                                                  float* __restrict__ out) {
    __shared__ float sWo[1024];
    __shared__ float sWc[32 * NTT];
    int tid = threadIdx.x;
    for (int i = tid; i < 1024; i += 256) sWo[i] = Wout[i];
    for (int i = tid; i < 32 * NTT; i += 256) sWc[i] = Wc[i];
    __syncthreads();
    int lane = tid & 31;
    int n = blockIdx.x * 8 + (tid >> 5);
    float f = f0[n * CC + lane];
    float hs = 0.0f;
#pragma unroll
    for (int c = 0; c < 32; c++)
        hs = fmaf(__shfl_sync(FULL, f, c), sWo[c * 32 + lane], hs);
    out[n * CC + lane] = hs;
    float cs = 0.0f;
#pragma unroll
    for (int c = 0; c < 32; c++) {
        float hv = __shfl_sync(FULL, hs, c);
        float wc = (lane < NTT) ? sWc[c * NTT + lane] : 0.0f;
        cs = fmaf(hv, wc, cs);
    }
    if (lane < NTT) out[NN * CC + n * NTT + lane] = cs;
}

// ---------------- host ----------------
extern "C" void kernel_launch(void* const* d_in, const int* in_sizes, int n_in,
                              void* d_out, int out_size) {
    const float* pos       = (const float*)d_in[0];
    const float* node_l0   = (const float*)d_in[1];
    const float* edge_feat = (const float*)d_in[2];
    const int*   edge_src  = (const int*)d_in[3];
    const int*   edge_dst  = (const int*)d_in[4];
    const float* Wr1       = (const float*)d_in[5];
    const float* br1       = (const float*)d_in[6];
    const float* Wr2       = (const float*)d_in[7];
    const float* Wq        = (const float*)d_in[8];
    const float* Wk        = (const float*)d_in[9];
    const float* Ws0       = (const float*)d_in[10];
    const float* Ws1       = (const float*)d_in[11];
    const float* Ws2       = (const float*)d_in[12];
    const float* Wsk       = (const float*)d_in[13];
    const float* Wout      = (const float*)d_in[14];
    const float* Wc        = (const float*)d_in[15];
    float* out = (float*)d_out;

    void *pf0, *pf1, *pf2, *pM;
    cudaGetSymbolAddress(&pf0, g_f0);
    cudaGetSymbolAddress(&pf1, g_f1);
    cudaGetSymbolAddress(&pf2, g_f2);
    cudaGetSymbolAddress(&pM, g_M);
    float* f0a = (float*)pf0;
    float* f0b = f0a + (size_t)NN * CC;
    float* f1a = (float*)pf1;
    float* f1b = f1a + (size_t)NN * CC * 3;
    float* f2a = (float*)pf2;
    float* f2b = f2a + (size_t)NN * CC * 5;
    float* M0 = (float*)pM;
    float* M1 = M0 + 32 * 128;

    mprep_kernel<<<1, 64>>>(Wq, Wk);
    hist_kernel<<<EE / 256, 256>>>(edge_dst);
    scan_kernel<<<1, 1024>>>();
    scatter_geo_kernel<<<EE / 256, 256>>>(pos, edge_src, edge_dst);

    const int FGRID = 940;   // grid-stride: ~4 nodes per warp, amortizes 33KB weight smem load

    // ---- layer 0 (f1 = f2 = 0) ----
    vn_kernel<<<NN / 8, 256>>>(M0, node_l0);
    fused_kernel<true><<<FGRID, 256>>>(edge_feat, Wr1, br1, Wr2,
                                       node_l0, nullptr, nullptr);
    selfmix_kernel<<<NN / 8, 256>>>(Ws0, Ws1, Ws2, Wsk, node_l0, f0a, f1a, f2a);

    // ---- layer 1 ----
    vn_kernel<<<NN / 8, 256>>>(M1, f0a);
    fused_kernel<false><<<FGRID, 256>>>(edge_feat, Wr1 + 33 * 32, br1 + 32, Wr2 + 32 * 224,
                                        f0a, f1a, f2a);
    selfmix_kernel<<<NN / 8, 256>>>(Ws0 + 1024, Ws1 + 1024, Ws2 + 1024, Wsk + 1024,
                                    f0a, f0b, f1b, f2b);

    out_kernel<<<NN / 8, 256>>>(Wout, Wc, f0b, out);
}